// round 7
// baseline (speedup 1.0000x reference)
#include <cuda_runtime.h>

// ScatterLoss fused kernel — R4 structure + KREP=2 replicated atomic tables.
//   loss = (||S_tot||^2 - sum_c ||S_c||^2) / (N^2 - sum_c n_c^2)

#define D_DIM 256
#define C_PAD 128      // labels in [0,100)
#define NTHR  256      // 8 warps/CTA, 2 rows/warp -> 16 rows/CTA
#define KREP  2
#define SLAB  (C_PAD * D_DIM)

__device__ float    g_csum[KREP * SLAB];    // zeroed at load; re-zeroed by tail
__device__ int      g_ccnt[KREP][C_PAD];
__device__ unsigned g_done;

__device__ __forceinline__ void red_v4(float* p, float x, float y, float z, float w) {
    asm volatile("red.global.add.v4.f32 [%0], {%1, %2, %3, %4};"
                 :: "l"(p), "f"(x), "f"(y), "f"(z), "f"(w) : "memory");
}

__global__ __launch_bounds__(NTHR, 4)
void fused_k(const float* __restrict__ e, const int* __restrict__ y,
             int N, float* __restrict__ out) {
    const int lane = threadIdx.x & 31;
    const int w    = (blockIdx.x * NTHR + threadIdx.x) >> 5;   // global warp id
    const int rep  = blockIdx.x & (KREP - 1);
    float* csum = g_csum + rep * SLAB;
    int*   ccnt = g_ccnt[rep];

    // ---- Phase 1: warp w handles rows 2w, 2w+1 ------------------------------
    const int r0 = 2 * w, r1 = 2 * w + 1;
    if (r0 < N) {
        const bool has1 = (r1 < N);
        int c0 = y[r0];
        int c1 = has1 ? y[r1] : -1;

        const float4* e0 = (const float4*)(e + (size_t)r0 * D_DIM);
        const float4* e1 = (const float4*)(e + (size_t)r1 * D_DIM);
        float4 a0 = e0[lane];
        float4 b0 = e0[lane + 32];
        float4 a1, b1;
        if (has1) { a1 = e1[lane]; b1 = e1[lane + 32]; }
        else      { a1 = make_float4(0,0,0,0); b1 = a1; }

        float s0 = a0.x*a0.x + a0.y*a0.y + a0.z*a0.z + a0.w*a0.w
                 + b0.x*b0.x + b0.y*b0.y + b0.z*b0.z + b0.w*b0.w;
        float s1 = a1.x*a1.x + a1.y*a1.y + a1.z*a1.z + a1.w*a1.w
                 + b1.x*b1.x + b1.y*b1.y + b1.z*b1.z + b1.w*b1.w;
        #pragma unroll
        for (int o = 16; o > 0; o >>= 1) {
            s0 += __shfl_xor_sync(0xffffffffu, s0, o);
            s1 += __shfl_xor_sync(0xffffffffu, s1, o);
        }
        float q0 = rsqrtf(s0);
        float q1 = rsqrtf(s1);

        if ((unsigned)c0 < C_PAD) {
            float* d0 = csum + c0 * D_DIM + lane * 4;
            red_v4(d0,       a0.x*q0, a0.y*q0, a0.z*q0, a0.w*q0);
            red_v4(d0 + 128, b0.x*q0, b0.y*q0, b0.z*q0, b0.w*q0);
            if (lane == 0) atomicAdd(&ccnt[c0], 1);
        }
        if ((unsigned)c1 < C_PAD) {
            float* d1 = csum + c1 * D_DIM + lane * 4;
            red_v4(d1,       a1.x*q1, a1.y*q1, a1.z*q1, a1.w*q1);
            red_v4(d1 + 128, b1.x*q1, b1.y*q1, b1.z*q1, b1.w*q1);
            if (lane == 1) atomicAdd(&ccnt[c1], 1);
        }
    }

    // ---- Elect last block ---------------------------------------------------
    __shared__ unsigned s_rank;
    __threadfence();
    __syncthreads();
    if (threadIdx.x == 0) s_rank = atomicAdd(&g_done, 1u);
    __syncthreads();
    if (s_rank != gridDim.x - 1) return;

    // ---- Phase 2: finalize (last block only) --------------------------------
    // thread (g = tid>>6, t = tid&63): classes g, g+4, ...; cols 4t..4t+3.
    const int tid = threadIdx.x;
    const int t   = tid & 63;
    const int g   = tid >> 6;

    const float4* csum4 = (const float4*)g_csum;
    float4 tot = make_float4(0,0,0,0);
    float  sqs = 0.0f;
    #pragma unroll 8
    for (int c = g; c < C_PAD; c += 4) {
        float4 v0 = __ldcg(&csum4[c * 64 + t]);
        float4 v1 = __ldcg(&csum4[SLAB/4 + c * 64 + t]);
        float4 v;
        v.x = v0.x + v1.x; v.y = v0.y + v1.y;
        v.z = v0.z + v1.z; v.w = v0.w + v1.w;
        tot.x += v.x; tot.y += v.y; tot.z += v.z; tot.w += v.w;
        sqs   += v.x*v.x + v.y*v.y + v.z*v.z + v.w*v.w;
    }

    __shared__ float4 s_tot[4][64];
    __shared__ float  s_red[NTHR];
    __shared__ float  s_cnt[NTHR];
    s_tot[g][t] = tot;
    s_red[tid]  = -sqs;

    float cc = 0.0f;
    if (tid < C_PAD)
        cc = (float)(__ldcg(&g_ccnt[0][tid]) + __ldcg(&g_ccnt[1][tid]));
    s_cnt[tid] = cc * cc;
    __syncthreads();

    if (tid < 64) {
        float4 T;
        T.x = s_tot[0][tid].x + s_tot[1][tid].x + s_tot[2][tid].x + s_tot[3][tid].x;
        T.y = s_tot[0][tid].y + s_tot[1][tid].y + s_tot[2][tid].y + s_tot[3][tid].y;
        T.z = s_tot[0][tid].z + s_tot[1][tid].z + s_tot[2][tid].z + s_tot[3][tid].z;
        T.w = s_tot[0][tid].w + s_tot[1][tid].w + s_tot[2][tid].w + s_tot[3][tid].w;
        s_red[tid] += T.x*T.x + T.y*T.y + T.z*T.z + T.w*T.w;
    }
    __syncthreads();

    #pragma unroll
    for (int o = NTHR / 2; o > 0; o >>= 1) {
        if (tid < o) {
            s_red[tid] += s_red[tid + o];
            s_cnt[tid] += s_cnt[tid + o];
        }
        __syncthreads();
    }

    if (tid == 0) {
        double num = (double)s_red[0];
        double den = (double)N * (double)N - (double)s_cnt[0];
        out[0] = (float)(num / den);
    }

    // ---- Re-zero scratch for next graph replay ------------------------------
    float4* z = (float4*)g_csum;
    #pragma unroll 4
    for (int i = tid; i < KREP * SLAB / 4; i += NTHR)
        z[i] = make_float4(0.f, 0.f, 0.f, 0.f);
    if (tid < C_PAD) { g_ccnt[0][tid] = 0; g_ccnt[1][tid] = 0; }
    if (tid == 0)    g_done = 0;
}

extern "C" void kernel_launch(void* const* d_in, const int* in_sizes, int n_in,
                              void* d_out, int out_size) {
    const float* e   = (const float*)d_in[0];
    const int*   y   = (const int*)d_in[1];
    float*       out = (float*)d_out;
    int N = in_sizes[1];

    int rows_per_blk = (NTHR / 32) * 2;               // 16
    int nblk = (N + rows_per_blk - 1) / rows_per_blk; // 512 for N=8192
    fused_k<<<nblk, NTHR>>>(e, y, N, out);
}

// round 8
// speedup vs baseline: 1.2635x; 1.2635x over previous
#include <cuda_runtime.h>

// ScatterLoss fused kernel — R4 structure with 1024-thread CTAs:
//   loss = (||S_tot||^2 - sum_c ||S_c||^2) / (N^2 - sum_c n_c^2)
// Phase 1: 32 warps/CTA, 2 rows/warp, batched loads. 128 CTAs = 1 wave.
// Phase 2: last block (1024 threads) finalizes + re-zeros: 4x faster tail.

#define D_DIM 256
#define C_PAD 128      // labels in [0,100)
#define NTHR  1024     // 32 warps/CTA, 2 rows/warp -> 64 rows/CTA

__device__ float    g_csum[C_PAD * D_DIM];  // zeroed at load; re-zeroed by tail
__device__ int      g_ccnt[C_PAD];
__device__ unsigned g_done;

__device__ __forceinline__ void red_v4(float* p, float x, float y, float z, float w) {
    asm volatile("red.global.add.v4.f32 [%0], {%1, %2, %3, %4};"
                 :: "l"(p), "f"(x), "f"(y), "f"(z), "f"(w) : "memory");
}

__global__ __launch_bounds__(NTHR, 1)
void fused_k(const float* __restrict__ e, const int* __restrict__ y,
             int N, float* __restrict__ out) {
    const int lane = threadIdx.x & 31;
    const int w    = (blockIdx.x * NTHR + threadIdx.x) >> 5;   // global warp id

    // ---- Phase 1: warp w handles rows 2w, 2w+1 ------------------------------
    const int r0 = 2 * w, r1 = 2 * w + 1;
    if (r0 < N) {
        const bool has1 = (r1 < N);
        int c0 = y[r0];
        int c1 = has1 ? y[r1] : -1;

        const float4* e0 = (const float4*)(e + (size_t)r0 * D_DIM);
        const float4* e1 = (const float4*)(e + (size_t)r1 * D_DIM);
        float4 a0 = e0[lane];
        float4 b0 = e0[lane + 32];
        float4 a1, b1;
        if (has1) { a1 = e1[lane]; b1 = e1[lane + 32]; }
        else      { a1 = make_float4(0,0,0,0); b1 = a1; }

        float s0 = a0.x*a0.x + a0.y*a0.y + a0.z*a0.z + a0.w*a0.w
                 + b0.x*b0.x + b0.y*b0.y + b0.z*b0.z + b0.w*b0.w;
        float s1 = a1.x*a1.x + a1.y*a1.y + a1.z*a1.z + a1.w*a1.w
                 + b1.x*b1.x + b1.y*b1.y + b1.z*b1.z + b1.w*b1.w;
        #pragma unroll
        for (int o = 16; o > 0; o >>= 1) {
            s0 += __shfl_xor_sync(0xffffffffu, s0, o);
            s1 += __shfl_xor_sync(0xffffffffu, s1, o);
        }
        float q0 = rsqrtf(s0);
        float q1 = rsqrtf(s1);

        if ((unsigned)c0 < C_PAD) {
            float* d0 = g_csum + c0 * D_DIM + lane * 4;
            red_v4(d0,       a0.x*q0, a0.y*q0, a0.z*q0, a0.w*q0);
            red_v4(d0 + 128, b0.x*q0, b0.y*q0, b0.z*q0, b0.w*q0);
            if (lane == 0) atomicAdd(&g_ccnt[c0], 1);
        }
        if ((unsigned)c1 < C_PAD) {
            float* d1 = g_csum + c1 * D_DIM + lane * 4;
            red_v4(d1,       a1.x*q1, a1.y*q1, a1.z*q1, a1.w*q1);
            red_v4(d1 + 128, b1.x*q1, b1.y*q1, b1.z*q1, b1.w*q1);
            if (lane == 1) atomicAdd(&g_ccnt[c1], 1);
        }
    }

    // ---- Elect last block ---------------------------------------------------
    __shared__ unsigned s_rank;
    __threadfence();
    __syncthreads();
    if (threadIdx.x == 0) s_rank = atomicAdd(&g_done, 1u);
    __syncthreads();
    if (s_rank != gridDim.x - 1) return;

    // ---- Phase 2: finalize (last block, 1024 threads) -----------------------
    // thread (g = tid>>6 in 0..15, t = tid&63): classes g, g+16, ...; cols 4t..4t+3.
    const int tid = threadIdx.x;
    const int t   = tid & 63;
    const int g   = tid >> 6;

    const float4* csum4 = (const float4*)g_csum;
    float4 tot = make_float4(0,0,0,0);
    float  sqs = 0.0f;
    #pragma unroll
    for (int c = g; c < C_PAD; c += 16) {   // 8 independent float4 loads
        float4 v = __ldcg(&csum4[c * 64 + t]);
        tot.x += v.x; tot.y += v.y; tot.z += v.z; tot.w += v.w;
        sqs   += v.x*v.x + v.y*v.y + v.z*v.z + v.w*v.w;
    }

    __shared__ float4 s_tot[16][64];
    __shared__ float  s_red[NTHR];
    __shared__ float  s_cnt[NTHR];
    s_tot[g][t] = tot;
    s_red[tid]  = -sqs;

    float cc = (tid < C_PAD) ? (float)__ldcg(&g_ccnt[tid]) : 0.0f;
    s_cnt[tid] = cc * cc;
    __syncthreads();

    if (tid < 64) {
        float4 T = make_float4(0,0,0,0);
        #pragma unroll
        for (int gg = 0; gg < 16; gg++) {
            T.x += s_tot[gg][tid].x;
            T.y += s_tot[gg][tid].y;
            T.z += s_tot[gg][tid].z;
            T.w += s_tot[gg][tid].w;
        }
        s_red[tid] += T.x*T.x + T.y*T.y + T.z*T.z + T.w*T.w;
    }
    __syncthreads();

    #pragma unroll
    for (int o = NTHR / 2; o > 0; o >>= 1) {
        if (tid < o) {
            s_red[tid] += s_red[tid + o];
            s_cnt[tid] += s_cnt[tid + o];
        }
        __syncthreads();
    }

    if (tid == 0) {
        double num = (double)s_red[0];
        double den = (double)N * (double)N - (double)s_cnt[0];
        out[0] = (float)(num / den);
    }

    // ---- Re-zero scratch for next graph replay (1024-wide) ------------------
    float4* z = (float4*)g_csum;
    #pragma unroll
    for (int i = tid; i < C_PAD * D_DIM / 4; i += NTHR)
        z[i] = make_float4(0.f, 0.f, 0.f, 0.f);
    if (tid < C_PAD) g_ccnt[tid] = 0;
    if (tid == 0)    g_done = 0;
}

extern "C" void kernel_launch(void* const* d_in, const int* in_sizes, int n_in,
                              void* d_out, int out_size) {
    const float* e   = (const float*)d_in[0];
    const int*   y   = (const int*)d_in[1];
    float*       out = (float*)d_out;
    int N = in_sizes[1];

    int rows_per_blk = (NTHR / 32) * 2;               // 64
    int nblk = (N + rows_per_blk - 1) / rows_per_blk; // 128 for N=8192
    fused_k<<<nblk, NTHR>>>(e, y, N, out);
}